// round 1
// baseline (speedup 1.0000x reference)
#include <cuda_runtime.h>

#define B_   8
#define V_   200
#define T_   128
#define NBLK (B_ * V_)          // 1600

// Scratch: q/k/v in layout [b][v][o=h*8+d][t], o in 0..63, t in 0..127
// size = 8*200*64*128 = 13,107,200 floats each (~52 MB)
__device__ float g_q[13107200];
__device__ float g_k[13107200];
__device__ float g_v[13107200];

// ---------------------------------------------------------------------------
// Kernel 1: fused channel-concat + Q/K/V 1x1-conv projections
// one block per (b,v); smem: xt[128][128] + W[192][128] + bias[192]
// ---------------------------------------------------------------------------
extern __shared__ float sm1[];
__global__ __launch_bounds__(512, 1) void qkv_kernel(
    const float* __restrict__ x,  const float* __restrict__ tem,
    const float* __restrict__ Wq, const float* __restrict__ bq,
    const float* __restrict__ Wk, const float* __restrict__ bk,
    const float* __restrict__ Wv, const float* __restrict__ bv)
{
    float* xs = sm1;                  // [c][t]   16384 floats
    float* ws = sm1 + 16384;          // [o][c]   24576 floats (q|k|v stacked)
    float* bs = sm1 + 16384 + 24576;  // [192]

    const int tid = threadIdx.x;
    const int blk = blockIdx.x;
    const int b = blk / V_, v = blk % V_;

    for (int i = tid; i < 8192; i += 512) ws[i]         = Wq[i];
    for (int i = tid; i < 8192; i += 512) ws[8192 + i]  = Wk[i];
    for (int i = tid; i < 8192; i += 512) ws[16384 + i] = Wv[i];
    if (tid < 64) { bs[tid] = bq[tid]; bs[64 + tid] = bk[tid]; bs[128 + tid] = bv[tid]; }

    // concat: channels 0..63 from x, 64..127 from tem (T equal, so "last T" = all)
    for (int i = tid; i < 16384; i += 512) {
        int c = i >> 7, t = i & 127;
        const float* src = (c < 64) ? x : tem;
        int cc = c & 63;
        xs[i] = src[(((b << 6) + cc) * V_ + v) * T_ + t];
    }
    __syncthreads();

    const int tx = tid & 31, ty = tid >> 5;   // ty: 0..15
    const int t0 = tx * 4;

    float acc[12][4];
#pragma unroll
    for (int j = 0; j < 12; ++j) {
        float bb = bs[ty + 16 * j];
        acc[j][0] = bb; acc[j][1] = bb; acc[j][2] = bb; acc[j][3] = bb;
    }

    for (int cc = 0; cc < 128; cc += 4) {
        float4 x0 = *(const float4*)&xs[(cc + 0) * 128 + t0];
        float4 x1 = *(const float4*)&xs[(cc + 1) * 128 + t0];
        float4 x2 = *(const float4*)&xs[(cc + 2) * 128 + t0];
        float4 x3 = *(const float4*)&xs[(cc + 3) * 128 + t0];
#pragma unroll
        for (int j = 0; j < 12; ++j) {
            int o = ty + 16 * j;
            float4 w = *(const float4*)&ws[o * 128 + cc];
            acc[j][0] += w.x * x0.x + w.y * x1.x + w.z * x2.x + w.w * x3.x;
            acc[j][1] += w.x * x0.y + w.y * x1.y + w.z * x2.y + w.w * x3.y;
            acc[j][2] += w.x * x0.z + w.y * x1.z + w.z * x2.z + w.w * x3.z;
            acc[j][3] += w.x * x0.w + w.y * x1.w + w.z * x2.w + w.w * x3.w;
        }
    }

    const long obase = (long)blk * 8192 + t0;
#pragma unroll
    for (int j = 0; j < 12; ++j) {
        int o = ty + 16 * j;
        int od = o & 63;
        float* dst = (o < 64) ? g_q : (o < 128 ? g_k : g_v);
        float4 r;
        r.x = acc[j][0]; r.y = acc[j][1]; r.z = acc[j][2]; r.w = acc[j][3];
        *(float4*)&dst[obase + od * 128] = r;
    }
}

// ---------------------------------------------------------------------------
// Kernel 2: causal attention (online softmax) + head merge + out-proj + ReLU
// one block per (b,v); smem: Q,K,V,AO [64][128] each + Wo[64][64] + bo[64]
// ---------------------------------------------------------------------------
extern __shared__ float sm2[];
__global__ __launch_bounds__(512, 1) void attn_kernel(
    const float* __restrict__ Wo, const float* __restrict__ bo,
    float* __restrict__ out)
{
    float* qs  = sm2;
    float* ks  = sm2 + 8192;
    float* vs  = sm2 + 16384;
    float* ao  = sm2 + 24576;
    float* wo  = sm2 + 32768;   // 4096
    float* bos = sm2 + 36864;   // 64

    const int tid = threadIdx.x;
    const int blk = blockIdx.x;
    const int b = blk / V_, v = blk % V_;
    const long base = (long)blk * 8192;

    for (int i = tid; i < 2048; i += 512) {
        ((float4*)qs)[i] = ((const float4*)(g_q + base))[i];
        ((float4*)ks)[i] = ((const float4*)(g_k + base))[i];
        ((float4*)vs)[i] = ((const float4*)(g_v + base))[i];
    }
    for (int i = tid; i < 4096; i += 512) wo[i] = Wo[i];
    if (tid < 64) bos[tid] = bo[tid];
    __syncthreads();

    const int t  = tid & 127;
    const int hh = tid >> 7;     // 0..3, two passes cover 8 heads

#pragma unroll
    for (int hp = 0; hp < 2; ++hp) {
        const int h = hh + 4 * hp;
        const float* kb = ks + h * 8 * 128;
        const float* vb = vs + h * 8 * 128;

        float qd[8];
#pragma unroll
        for (int d = 0; d < 8; ++d) qd[d] = qs[(h * 8 + d) * 128 + t];

        float m = -3.0e38f, l = 0.f;
        float acc[8] = {0.f, 0.f, 0.f, 0.f, 0.f, 0.f, 0.f, 0.f};

        for (int s = 0; s <= t; ++s) {        // causal: skip s>t (== mask of -32767)
            float sc = qd[0] * kb[s];
#pragma unroll
            for (int d = 1; d < 8; ++d) sc += qd[d] * kb[d * 128 + s];
            sc *= 0.35355339059327373f;       // 1/sqrt(8)
            float nm = fmaxf(m, sc);
            float c1 = __expf(m - nm);
            float p  = __expf(sc - nm);
            l = l * c1 + p;
            m = nm;
#pragma unroll
            for (int d = 0; d < 8; ++d) acc[d] = acc[d] * c1 + p * vb[d * 128 + s];
        }
        float inv = 1.0f / l;
#pragma unroll
        for (int d = 0; d < 8; ++d) ao[(h * 8 + d) * 128 + t] = acc[d] * inv;
    }
    __syncthreads();

    // out projection (64x64) + ReLU, register-tiled 4o x 4t
    const int tx = tid & 31, ty = tid >> 5;
    const int t0 = tx * 4;
    float oa[4][4];
#pragma unroll
    for (int j = 0; j < 4; ++j) {
        float bb = bos[ty + 16 * j];
        oa[j][0] = bb; oa[j][1] = bb; oa[j][2] = bb; oa[j][3] = bb;
    }
    for (int ic = 0; ic < 64; ic += 4) {
        float4 a0 = *(const float4*)&ao[(ic + 0) * 128 + t0];
        float4 a1 = *(const float4*)&ao[(ic + 1) * 128 + t0];
        float4 a2 = *(const float4*)&ao[(ic + 2) * 128 + t0];
        float4 a3 = *(const float4*)&ao[(ic + 3) * 128 + t0];
#pragma unroll
        for (int j = 0; j < 4; ++j) {
            int o = ty + 16 * j;
            float4 w = *(const float4*)&wo[o * 64 + ic];
            oa[j][0] += w.x * a0.x + w.y * a1.x + w.z * a2.x + w.w * a3.x;
            oa[j][1] += w.x * a0.y + w.y * a1.y + w.z * a2.y + w.w * a3.y;
            oa[j][2] += w.x * a0.z + w.y * a1.z + w.z * a2.z + w.w * a3.z;
            oa[j][3] += w.x * a0.w + w.y * a1.w + w.z * a2.w + w.w * a3.w;
        }
    }
#pragma unroll
    for (int j = 0; j < 4; ++j) {
        int o = ty + 16 * j;
        float4 r;
        r.x = fmaxf(oa[j][0], 0.f); r.y = fmaxf(oa[j][1], 0.f);
        r.z = fmaxf(oa[j][2], 0.f); r.w = fmaxf(oa[j][3], 0.f);
        *(float4*)&out[(((long)b * 64 + o) * V_ + v) * T_ + t0] = r;
    }
}

// ---------------------------------------------------------------------------
extern "C" void kernel_launch(void* const* d_in, const int* in_sizes, int n_in,
                              void* d_out, int out_size)
{
    (void)in_sizes; (void)n_in; (void)out_size;
    const float* x  = (const float*)d_in[0];
    const float* te = (const float*)d_in[1];
    const float* Wq = (const float*)d_in[2];
    const float* bq = (const float*)d_in[3];
    const float* Wk = (const float*)d_in[4];
    const float* bk = (const float*)d_in[5];
    const float* Wv = (const float*)d_in[6];
    const float* bv = (const float*)d_in[7];
    const float* Wo = (const float*)d_in[8];
    const float* bo = (const float*)d_in[9];
    float* out = (float*)d_out;

    const int smem1 = (16384 + 24576 + 192) * 4;      // 164,608 B
    const int smem2 = (32768 + 4096 + 64) * 4;        // 147,712 B

    cudaFuncSetAttribute(qkv_kernel, cudaFuncAttributeMaxDynamicSharedMemorySize, smem1);
    cudaFuncSetAttribute(attn_kernel, cudaFuncAttributeMaxDynamicSharedMemorySize, smem2);

    qkv_kernel<<<NBLK, 512, smem1>>>(x, te, Wq, bq, Wk, bk, Wv, bv);
    attn_kernel<<<NBLK, 512, smem2>>>(Wo, bo, out);
}

// round 2
// speedup vs baseline: 1.4600x; 1.4600x over previous
#include <cuda_runtime.h>

#define B_   8
#define V_   200
#define T_   128
#define NBLK (B_ * V_)          // 1600

// ---------------------------------------------------------------------------
// Fully fused: concat + QKV projection + causal attention + out-proj + ReLU.
// One block per (b,v). 512 threads.
//
// smem layout (floats):
//   [0,16384)      xs  : concat input [c=128][t=128]  (reused as ao later)
//   [16384,24576)  ws  : current projection weights [64][128] (reused as wo)
//   [24576,32768)  qs  : Q [o=64][t=128]
//   [32768,40960)  ks  : K
//   [40960,49152)  vs  : V
//   [49152,49408)  bias: bq|bk|bv|bo
// total 49408 floats = 197,632 B  -> 1 CTA/SM
// ---------------------------------------------------------------------------
extern __shared__ float sm[];
__global__ __launch_bounds__(512, 1) void tatt_fused(
    const float* __restrict__ x,  const float* __restrict__ tem,
    const float* __restrict__ Wq, const float* __restrict__ bq,
    const float* __restrict__ Wk, const float* __restrict__ bk,
    const float* __restrict__ Wv, const float* __restrict__ bv,
    const float* __restrict__ Wo, const float* __restrict__ bo,
    float* __restrict__ out)
{
    float* xs   = sm;
    float* ws   = sm + 16384;
    float* bias = sm + 49152;

    const int tid = threadIdx.x;
    const int blk = blockIdx.x;
    const int b = blk / V_, v = blk % V_;

    // ---- stage concat input [c][t] ----
    for (int i = tid; i < 16384; i += 512) {
        int c = i >> 7, t = i & 127;
        const float* src = (c < 64) ? x : tem;
        xs[i] = src[(((b << 6) + (c & 63)) * V_ + v) * T_ + t];
    }
    if (tid < 64) {
        bias[tid]       = bq[tid];
        bias[64 + tid]  = bk[tid];
        bias[128 + tid] = bv[tid];
        bias[192 + tid] = bo[tid];
    }

    // ---- three projections, register-tiled 4o x 4t ----
    const int tx = tid & 31, ty = tid >> 5;   // ty 0..15
    const int t0 = tx * 4;

    const float* Wsrc[3] = {Wq, Wk, Wv};
#pragma unroll
    for (int p = 0; p < 3; ++p) {
        float* dst = sm + 24576 + p * 8192;   // qs / ks / vs
        for (int i = tid; i < 8192; i += 512) ws[i] = Wsrc[p][i];
        __syncthreads();

        float acc[4][4];
#pragma unroll
        for (int j = 0; j < 4; ++j) {
            float bb = bias[p * 64 + ty + 16 * j];
            acc[j][0] = bb; acc[j][1] = bb; acc[j][2] = bb; acc[j][3] = bb;
        }
        for (int cc = 0; cc < 128; cc += 4) {
            float4 x0 = *(const float4*)&xs[(cc + 0) * 128 + t0];
            float4 x1 = *(const float4*)&xs[(cc + 1) * 128 + t0];
            float4 x2 = *(const float4*)&xs[(cc + 2) * 128 + t0];
            float4 x3 = *(const float4*)&xs[(cc + 3) * 128 + t0];
#pragma unroll
            for (int j = 0; j < 4; ++j) {
                float4 w = *(const float4*)&ws[(ty + 16 * j) * 128 + cc];
                acc[j][0] += w.x * x0.x + w.y * x1.x + w.z * x2.x + w.w * x3.x;
                acc[j][1] += w.x * x0.y + w.y * x1.y + w.z * x2.y + w.w * x3.y;
                acc[j][2] += w.x * x0.z + w.y * x1.z + w.z * x2.z + w.w * x3.z;
                acc[j][3] += w.x * x0.w + w.y * x1.w + w.z * x2.w + w.w * x3.w;
            }
        }
#pragma unroll
        for (int j = 0; j < 4; ++j) {
            float4 r;
            r.x = acc[j][0]; r.y = acc[j][1]; r.z = acc[j][2]; r.w = acc[j][3];
            *(float4*)&dst[(ty + 16 * j) * 128 + t0] = r;
        }
        __syncthreads();
    }

    // ---- load Wo into ws region (safe: projections done) ----
    for (int i = tid; i < 4096; i += 512) ws[i] = Wo[i];

    // ---- causal attention, no-max softmax (scores are bounded), s by 4 ----
    // warp w: head-group g = w&3 (heads g, g+4), t-range r = w>>2.
    // This puts the four longest warps (t in [96,128)) on DIFFERENT SMSPs.
    const int w    = tid >> 5, lane = tid & 31;
    const int g    = w & 3;
    const int t    = (w >> 2) * 32 + lane;
    float* qs = sm + 24576;
    float* ks = sm + 32768;
    float* vs = sm + 40960;
    float* ao = xs;                       // reuse xs region

#pragma unroll
    for (int hp = 0; hp < 2; ++hp) {
        const int h = g + 4 * hp;
        const float* qb = qs + h * 1024;
        const float* kb = ks + h * 1024;
        const float* vb = vs + h * 1024;

        float qd[8];
#pragma unroll
        for (int d = 0; d < 8; ++d)
            qd[d] = qb[d * 128 + t] * 0.35355339059327373f;   // fold 1/sqrt(8)

        float l = 0.f;
        float a8[8] = {0.f,0.f,0.f,0.f,0.f,0.f,0.f,0.f};

        for (int s0 = 0; s0 <= t; s0 += 4) {
            float4 sc = make_float4(0.f, 0.f, 0.f, 0.f);
#pragma unroll
            for (int d = 0; d < 8; ++d) {
                float4 k4 = *(const float4*)&kb[d * 128 + s0];
                sc.x += qd[d] * k4.x;
                sc.y += qd[d] * k4.y;
                sc.z += qd[d] * k4.z;
                sc.w += qd[d] * k4.w;
            }
            float4 p;
            p.x = __expf(sc.x);                                // s0 <= t by loop cond
            p.y = (s0 + 1 <= t) ? __expf(sc.y) : 0.f;
            p.z = (s0 + 2 <= t) ? __expf(sc.z) : 0.f;
            p.w = (s0 + 3 <= t) ? __expf(sc.w) : 0.f;
            l += p.x + p.y + p.z + p.w;
#pragma unroll
            for (int d = 0; d < 8; ++d) {
                float4 v4 = *(const float4*)&vb[d * 128 + s0];
                a8[d] += p.x * v4.x + p.y * v4.y + p.z * v4.z + p.w * v4.w;
            }
        }
        float inv = 1.0f / l;
#pragma unroll
        for (int d = 0; d < 8; ++d)
            ao[(h * 8 + d) * 128 + t] = a8[d] * inv;
    }
    __syncthreads();

    // ---- out projection (64x64) + ReLU, register-tiled 4o x 4t ----
    float oa[4][4];
#pragma unroll
    for (int j = 0; j < 4; ++j) {
        float bb = bias[192 + ty + 16 * j];
        oa[j][0] = bb; oa[j][1] = bb; oa[j][2] = bb; oa[j][3] = bb;
    }
    for (int ic = 0; ic < 64; ic += 4) {
        float4 a0 = *(const float4*)&ao[(ic + 0) * 128 + t0];
        float4 a1 = *(const float4*)&ao[(ic + 1) * 128 + t0];
        float4 a2 = *(const float4*)&ao[(ic + 2) * 128 + t0];
        float4 a3 = *(const float4*)&ao[(ic + 3) * 128 + t0];
#pragma unroll
        for (int j = 0; j < 4; ++j) {
            float4 w4 = *(const float4*)&ws[(ty + 16 * j) * 64 + ic];
            oa[j][0] += w4.x * a0.x + w4.y * a1.x + w4.z * a2.x + w4.w * a3.x;
            oa[j][1] += w4.x * a0.y + w4.y * a1.y + w4.z * a2.y + w4.w * a3.y;
            oa[j][2] += w4.x * a0.z + w4.y * a1.z + w4.z * a2.z + w4.w * a3.z;
            oa[j][3] += w4.x * a0.w + w4.y * a1.w + w4.z * a2.w + w4.w * a3.w;
        }
    }
#pragma unroll
    for (int j = 0; j < 4; ++j) {
        int o = ty + 16 * j;
        float4 r;
        r.x = fmaxf(oa[j][0], 0.f); r.y = fmaxf(oa[j][1], 0.f);
        r.z = fmaxf(oa[j][2], 0.f); r.w = fmaxf(oa[j][3], 0.f);
        *(float4*)&out[(((long)b * 64 + o) * V_ + v) * T_ + t0] = r;
    }
}

// ---------------------------------------------------------------------------
extern "C" void kernel_launch(void* const* d_in, const int* in_sizes, int n_in,
                              void* d_out, int out_size)
{
    (void)in_sizes; (void)n_in; (void)out_size;
    const float* x  = (const float*)d_in[0];
    const float* te = (const float*)d_in[1];
    const float* Wq = (const float*)d_in[2];
    const float* bq = (const float*)d_in[3];
    const float* Wk = (const float*)d_in[4];
    const float* bk = (const float*)d_in[5];
    const float* Wv = (const float*)d_in[6];
    const float* bv = (const float*)d_in[7];
    const float* Wo = (const float*)d_in[8];
    const float* bo = (const float*)d_in[9];
    float* out = (float*)d_out;

    const int smem = 49408 * 4;   // 197,632 B
    cudaFuncSetAttribute(tatt_fused, cudaFuncAttributeMaxDynamicSharedMemorySize, smem);
    tatt_fused<<<NBLK, 512, smem>>>(x, te, Wq, bq, Wk, bk, Wv, bv, Wo, bo, out);
}

// round 3
// speedup vs baseline: 1.6883x; 1.1564x over previous
#include <cuda_runtime.h>

#define B_   8
#define V_   200
#define T_   128
#define NBLK (B_ * V_)          // 1600

typedef unsigned long long u64;

// ---- packed fp32x2 helpers (Blackwell sm_100a+: one issue slot, two FMAs) ----
__device__ __forceinline__ u64 pk2(float lo, float hi) {
    u64 r; asm("mov.b64 %0, {%1, %2};" : "=l"(r) : "f"(lo), "f"(hi)); return r;
}
__device__ __forceinline__ float2 upk2(u64 p) {
    float2 r; asm("mov.b64 {%0, %1}, %2;" : "=f"(r.x), "=f"(r.y) : "l"(p)); return r;
}
__device__ __forceinline__ u64 ffma2(u64 a, u64 b, u64 c) {
    u64 d; asm("fma.rn.f32x2 %0, %1, %2, %3;" : "=l"(d) : "l"(a), "l"(b), "l"(c)); return d;
}

// ---- smem layout (float offsets) ----
// XS: staged input transposed [t=128][pitch 132]  (reused later as ao [t][pitch 68])
// WS: current weights [64][128]                   (reused later as Wo [64][64])
// QS/KS/VS: [o=64][t=128]
#define XS    0
#define XP    132
#define WS    16896
#define QS    25088
#define KS    33280
#define VS    41472
#define BIAS  49664
#define SMF   49920          // total floats -> 199,680 bytes
#define AOP   68             // ao pitch

extern __shared__ float sm[];

__global__ __launch_bounds__(512, 1) void tatt_fused(
    const float* __restrict__ x,  const float* __restrict__ tem,
    const float* __restrict__ Wq, const float* __restrict__ bq,
    const float* __restrict__ Wk, const float* __restrict__ bk,
    const float* __restrict__ Wv, const float* __restrict__ bv,
    const float* __restrict__ Wo, const float* __restrict__ bo,
    float* __restrict__ out)
{
    float* xs   = sm + XS;
    float* ws   = sm + WS;
    float* bias = sm + BIAS;

    const int tid  = threadIdx.x;
    const int lane = tid & 31;
    const int w    = tid >> 5;
    const int blk  = blockIdx.x;
    const int b    = blk / V_, v = blk % V_;

    // ---- stage concat input TRANSPOSED: xs[t][c], pitch 132 ----
    for (int i = tid; i < 16384; i += 512) {
        int c = i >> 7, t = i & 127;                      // consecutive lanes -> consecutive t
        const float* src = (c < 64) ? x : tem;
        xs[t * XP + c] = src[(((b << 6) + (c & 63)) * V_ + v) * T_ + t];
    }
    if (tid < 64) {
        bias[tid]       = bq[tid];
        bias[64 + tid]  = bk[tid];
        bias[128 + tid] = bv[tid];
        bias[192 + tid] = bo[tid];
    }

    // projection thread mapping: o-oct og (8 outputs), t-pair (tl, tl+64)
    const int og = w >> 1;                    // 0..7
    const int tl = ((w & 1) << 5) + lane;     // 0..63

    // ---- three projections with f32x2 (acc holds even/odd-c partial sums) ----
    const float* Wsrc[3] = {Wq, Wk, Wv};
#pragma unroll
    for (int p = 0; p < 3; ++p) {
        __syncthreads();                       // prior readers of ws done
        for (int i = tid; i < 8192; i += 512) ws[i] = Wsrc[p][i];
        __syncthreads();

        u64 acc[8][2];
#pragma unroll
        for (int j = 0; j < 8; ++j) { acc[j][0] = 0ULL; acc[j][1] = 0ULL; }

#pragma unroll 4
        for (int c = 0; c < 128; c += 4) {
            ulonglong2 xa = *(const ulonglong2*)&xs[tl * XP + c];
            ulonglong2 xb = *(const ulonglong2*)&xs[(tl + 64) * XP + c];
#pragma unroll
            for (int j = 0; j < 8; ++j) {
                ulonglong2 wv = *(const ulonglong2*)&ws[(og * 8 + j) * 128 + c];
                acc[j][0] = ffma2(wv.x, xa.x, acc[j][0]);
                acc[j][0] = ffma2(wv.y, xa.y, acc[j][0]);
                acc[j][1] = ffma2(wv.x, xb.x, acc[j][1]);
                acc[j][1] = ffma2(wv.y, xb.y, acc[j][1]);
            }
        }

        float* dst = sm + QS + p * 8192;
#pragma unroll
        for (int j = 0; j < 8; ++j) {
            int o = og * 8 + j;
            float bb = bias[p * 64 + o];
            float2 la = upk2(acc[j][0]);
            float2 lb = upk2(acc[j][1]);
            dst[o * 128 + tl]      = bb + la.x + la.y;
            dst[o * 128 + tl + 64] = bb + lb.x + lb.y;
        }
    }
    __syncthreads();                           // q/k/v complete; xs free for reuse

    // ---- load Wo into ws (overlaps attention; ws not read until after next sync) ----
    for (int i = tid; i < 4096; i += 512) ws[i] = Wo[i];

    // ---- causal attention, balanced two-pass schedule, f32x2 over s ----
    // pass0: head g,   t = 32r + lane
    // pass1: head g+4, t = 127 - (32r + lane)
    // every warp: ~40 s-quad trips total -> no tail imbalance
    const int g = w & 3, r = w >> 2;
    float* qs = sm + QS;
    float* ks = sm + KS;
    float* vs = sm + VS;
    float* ao = xs;                            // [t][AOP]

#pragma unroll
    for (int hp = 0; hp < 2; ++hp) {
        const int h = g + 4 * hp;
        const int t = hp ? (127 - ((r << 5) + lane)) : ((r << 5) + lane);
        const float* qb = qs + h * 1024;
        const float* kb = ks + h * 1024;
        const float* vb = vs + h * 1024;

        u64 qd2[8];
#pragma unroll
        for (int d = 0; d < 8; ++d) {
            float qv = qb[d * 128 + t] * 0.35355339059327373f;   // fold 1/sqrt(8)
            qd2[d] = pk2(qv, qv);
        }

        float l = 0.f;
        u64 a2[8];
#pragma unroll
        for (int d = 0; d < 8; ++d) a2[d] = 0ULL;

        for (int s0 = 0; s0 <= t; s0 += 4) {
            u64 s01 = 0ULL, s23 = 0ULL;
#pragma unroll
            for (int d = 0; d < 8; ++d) {
                ulonglong2 kv = *(const ulonglong2*)&kb[d * 128 + s0];   // warp-uniform
                s01 = ffma2(qd2[d], kv.x, s01);
                s23 = ffma2(qd2[d], kv.y, s23);
            }
            float2 ea = upk2(s01), eb = upk2(s23);
            float p0 = __expf(ea.x);                              // s0 <= t guaranteed
            float p1 = (s0 + 1 <= t) ? __expf(ea.y) : 0.f;
            float p2 = (s0 + 2 <= t) ? __expf(eb.x) : 0.f;
            float p3 = (s0 + 3 <= t) ? __expf(eb.y) : 0.f;
            l += (p0 + p1) + (p2 + p3);
            u64 p01 = pk2(p0, p1), p23 = pk2(p2, p3);
#pragma unroll
            for (int d = 0; d < 8; ++d) {
                ulonglong2 vv = *(const ulonglong2*)&vb[d * 128 + s0];   // warp-uniform
                a2[d] = ffma2(p01, vv.x, a2[d]);
                a2[d] = ffma2(p23, vv.y, a2[d]);
            }
        }

        float inv = __fdividef(1.0f, l);
        float o8[8];
#pragma unroll
        for (int d = 0; d < 8; ++d) {
            float2 aa = upk2(a2[d]);
            o8[d] = (aa.x + aa.y) * inv;
        }
        // ao transposed row: [t][h*8 .. h*8+7], 16B-aligned
        float4 r0 = make_float4(o8[0], o8[1], o8[2], o8[3]);
        float4 r1 = make_float4(o8[4], o8[5], o8[6], o8[7]);
        *(float4*)&ao[t * AOP + h * 8]     = r0;
        *(float4*)&ao[t * AOP + h * 8 + 4] = r1;
    }
    __syncthreads();                           // ao + wo ready

    // ---- out projection (64x64) + ReLU with f32x2, same 8o x 2t tiling ----
    {
        u64 acc[8][2];
#pragma unroll
        for (int j = 0; j < 8; ++j) { acc[j][0] = 0ULL; acc[j][1] = 0ULL; }

#pragma unroll 4
        for (int c = 0; c < 64; c += 4) {
            ulonglong2 xa = *(const ulonglong2*)&ao[tl * AOP + c];
            ulonglong2 xb = *(const ulonglong2*)&ao[(tl + 64) * AOP + c];
#pragma unroll
            for (int j = 0; j < 8; ++j) {
                ulonglong2 wv = *(const ulonglong2*)&ws[(og * 8 + j) * 64 + c];
                acc[j][0] = ffma2(wv.x, xa.x, acc[j][0]);
                acc[j][0] = ffma2(wv.y, xa.y, acc[j][0]);
                acc[j][1] = ffma2(wv.x, xb.x, acc[j][1]);
                acc[j][1] = ffma2(wv.y, xb.y, acc[j][1]);
            }
        }

#pragma unroll
        for (int j = 0; j < 8; ++j) {
            int o = og * 8 + j;
            float bb = bias[192 + o];
            float2 la = upk2(acc[j][0]);
            float2 lb = upk2(acc[j][1]);
            float r0 = fmaxf(bb + la.x + la.y, 0.f);
            float r1 = fmaxf(bb + lb.x + lb.y, 0.f);
            long obase = (((long)b * 64 + o) * V_ + v) * T_;
            out[obase + tl]      = r0;
            out[obase + tl + 64] = r1;
        }
    }
}

// ---------------------------------------------------------------------------
extern "C" void kernel_launch(void* const* d_in, const int* in_sizes, int n_in,
                              void* d_out, int out_size)
{
    (void)in_sizes; (void)n_in; (void)out_size;
    const float* x  = (const float*)d_in[0];
    const float* te = (const float*)d_in[1];
    const float* Wq = (const float*)d_in[2];
    const float* bq = (const float*)d_in[3];
    const float* Wk = (const float*)d_in[4];
    const float* bk = (const float*)d_in[5];
    const float* Wv = (const float*)d_in[6];
    const float* bv = (const float*)d_in[7];
    const float* Wo = (const float*)d_in[8];
    const float* bo = (const float*)d_in[9];
    float* out = (float*)d_out;

    const int smem = SMF * 4;   // 199,680 B
    cudaFuncSetAttribute(tatt_fused, cudaFuncAttributeMaxDynamicSharedMemorySize, smem);
    tatt_fused<<<NBLK, 512, smem>>>(x, te, Wq, bq, Wk, bk, Wv, bv, Wo, bo, out);
}

// round 5
// speedup vs baseline: 2.1123x; 1.2512x over previous
#include <cuda_runtime.h>
#include <cuda_bf16.h>
#include <cstdint>

typedef unsigned long long u64;
typedef unsigned int       u32;

#define B_   8
#define V_   200
#define T_   128
#define NBLK (B_ * V_)          // 1600
#define KP   132                // Q/K/V smem pitch (conflict-free epilogue + aligned float4)

// ---- smem byte offsets ----
#define OF_AFH  0               // A frags hi: u32[8tt][8kg][4reg][32lane] = 32KB
#define OF_AFL  32768
#define OF_BFH  65536           // B frags hi: u32[8ot][8kg][2reg][32lane] = 16KB
#define OF_BFL  81920
#define OF_QS   98304           // fp32 [64][KP] = 33792 B
#define OF_KS   132096
#define OF_VS   165888
#define OF_BIAS 199680          // 256 floats
#define SMEM_TOTAL 200704

// ---- helpers ----
__device__ __forceinline__ u64 pk2(float lo, float hi) {
    u64 r; asm("mov.b64 %0, {%1, %2};" : "=l"(r) : "f"(lo), "f"(hi)); return r;
}
__device__ __forceinline__ float2 upk2(u64 p) {
    float2 r; asm("mov.b64 {%0, %1}, %2;" : "=f"(r.x), "=f"(r.y) : "l"(p)); return r;
}
__device__ __forceinline__ u64 ffma2(u64 a, u64 b, u64 c) {
    u64 d; asm("fma.rn.f32x2 %0, %1, %2, %3;" : "=l"(d) : "l"(a), "l"(b), "l"(c)); return d;
}
__device__ __forceinline__ u32 pack_bf(float a, float b) {
    __nv_bfloat162 h = __floats2bfloat162_rn(a, b);   // .x = a (low), .y = b (high)
    u32 r; asm("mov.b32 %0, %1;" : "=r"(r) : "r"(*(u32*)&h)); return r;
}
__device__ __forceinline__ float bfr(float a) {       // round-to-bf16, back to fp32
    return __bfloat162float(__float2bfloat16(a));
}
// m16n8k16 row.col bf16 -> f32, D += A*B
__device__ __forceinline__ void mma16816(float* c, const u32* a, const u32* b) {
    asm volatile(
        "mma.sync.aligned.m16n8k16.row.col.f32.bf16.bf16.f32 "
        "{%0,%1,%2,%3}, {%4,%5,%6,%7}, {%8,%9}, {%0,%1,%2,%3};"
        : "+f"(c[0]), "+f"(c[1]), "+f"(c[2]), "+f"(c[3])
        : "r"(a[0]), "r"(a[1]), "r"(a[2]), "r"(a[3]), "r"(b[0]), "r"(b[1]));
}

extern __shared__ char smc[];

__global__ __launch_bounds__(512, 1) void tatt_hmma(
    const float* __restrict__ x,  const float* __restrict__ tem,
    const float* __restrict__ Wq, const float* __restrict__ bq,
    const float* __restrict__ Wk, const float* __restrict__ bk,
    const float* __restrict__ Wv, const float* __restrict__ bv,
    const float* __restrict__ Wo, const float* __restrict__ bo,
    float* __restrict__ out)
{
    u32*   AFH  = (u32*)(smc + OF_AFH);
    u32*   AFL  = (u32*)(smc + OF_AFL);
    u32*   BFH  = (u32*)(smc + OF_BFH);
    u32*   BFL  = (u32*)(smc + OF_BFL);
    float* QS   = (float*)(smc + OF_QS);
    float* KS   = (float*)(smc + OF_KS);
    float* VS   = (float*)(smc + OF_VS);
    float* bias = (float*)(smc + OF_BIAS);

    const int tid = threadIdx.x, lane = tid & 31, w = tid >> 5;
    const int blk = blockIdx.x, b = blk / V_, v = blk % V_;

    if (tid < 64) {
        bias[tid]       = bq[tid];
        bias[64 + tid]  = bk[tid];
        bias[128 + tid] = bv[tid];
        bias[192 + tid] = bo[tid];
    }

    // ---- stage concat input as A-fragments (hi/lo bf16 split) ----
    // element (t, c): frag(tt=t>>4, kg=c>>4), lane_f=(t&7)*4+((c&15)>>1 &3),
    // reg=((t&15)>>3)+2*((c&15)>>3), halfword=c&1; lane XOR X=(t>>3)&3.
    for (int i = tid; i < 8192; i += 512) {
        int cp = i >> 7, t = i & 127;          // warp: fixed cp, 32 consecutive t
        int c0 = cp << 1;
        const float* src = (c0 < 64) ? x : tem;
        const float* pb = src + ((long)((b << 6) + (c0 & 63)) * V_ + v) * T_ + t;
        float g0 = pb[0];
        float g1 = pb[(long)V_ * T_];          // next channel
        int tt = t >> 4, kg = cp >> 3, tin = t & 15;
        int lane_f = ((tin & 7) << 2) + (cp & 3);
        int reg = (tin >> 3) + (((cp >> 2) & 1) << 1);
        int X = (t >> 3) & 3;
        int idx = (((tt << 3) + kg) * 4 + reg) * 32 + (lane_f ^ X);
        AFH[idx] = pack_bf(g0, g1);
        AFL[idx] = pack_bf(g0 - bfr(g0), g1 - bfr(g1));
    }

    // GEMM warp tiling: warp = (mt = w>>2) x (nq = w&3); m32 x n16 x k-full
    const int mt = w >> 2, nq = w & 3;
    const int gid = lane >> 2, tig = lane & 3;

    // ---- three projections ----
    const float* Wsrc[3] = {Wq, Wk, Wv};
    float* Dst[3] = {QS, KS, VS};
#pragma unroll 1
    for (int p = 0; p < 3; ++p) {
        // stage W[o][c] as B-fragments (hi/lo)
        for (int i = tid; i < 4096; i += 512) {
            int o = i >> 6, cp = i & 63;       // warp: fixed o, 32 consecutive cp
            float2 g = *(const float2*)(Wsrc[p] + o * 128 + (cp << 1));
            int kg = cp >> 3;
            int lane_f = ((o & 7) << 2) + (cp & 3);
            int reg = (cp >> 2) & 1;
            int X = ((cp >> 2) & 7) << 2;
            int idx = ((((o >> 3) << 3) + kg) * 2 + reg) * 32 + (lane_f ^ X);
            BFH[idx] = pack_bf(g.x, g.y);
            BFL[idx] = pack_bf(g.x - bfr(g.x), g.y - bfr(g.y));
        }
        __syncthreads();

        float acc[2][2][4];
#pragma unroll
        for (int m2 = 0; m2 < 2; ++m2)
#pragma unroll
            for (int n2 = 0; n2 < 2; ++n2)
#pragma unroll
                for (int j = 0; j < 4; ++j) acc[m2][n2][j] = 0.f;

#pragma unroll
        for (int kg = 0; kg < 8; ++kg) {
            u32 Ah[2][4], Al[2][4], Bh[2][2], Bl[2][2];
#pragma unroll
            for (int m2 = 0; m2 < 2; ++m2) {
                int tt = mt * 2 + m2;
#pragma unroll
                for (int r = 0; r < 4; ++r) {
                    int X = (tt * 2 + (r & 1)) & 3;
                    int idx = ((tt * 8 + kg) * 4 + r) * 32 + (lane ^ X);
                    Ah[m2][r] = AFH[idx];
                    Al[m2][r] = AFL[idx];
                }
            }
#pragma unroll
            for (int n2 = 0; n2 < 2; ++n2) {
                int ot = nq * 2 + n2;
#pragma unroll
                for (int r = 0; r < 2; ++r) {
                    int X = ((kg * 2 + r) & 7) << 2;
                    int idx = ((ot * 8 + kg) * 2 + r) * 32 + (lane ^ X);
                    Bh[n2][r] = BFH[idx];
                    Bl[n2][r] = BFL[idx];
                }
            }
#pragma unroll
            for (int m2 = 0; m2 < 2; ++m2)
#pragma unroll
                for (int n2 = 0; n2 < 2; ++n2) {
                    mma16816(acc[m2][n2], Ah[m2], Bh[n2]);
                    mma16816(acc[m2][n2], Ah[m2], Bl[n2]);
                    mma16816(acc[m2][n2], Al[m2], Bh[n2]);
                }
        }

        // epilogue: D[t][o] + bias -> dst[o][t], pitch KP (conflict-free)
        float* dst = Dst[p];
#pragma unroll
        for (int m2 = 0; m2 < 2; ++m2)
#pragma unroll
            for (int n2 = 0; n2 < 2; ++n2) {
                int t0 = ((mt * 2 + m2) << 4) + gid;
                int o0 = ((nq * 2 + n2) << 3) + (tig << 1);
                float b0 = bias[p * 64 + o0], b1 = bias[p * 64 + o0 + 1];
                dst[o0 * KP + t0]           = acc[m2][n2][0] + b0;
                dst[(o0 + 1) * KP + t0]     = acc[m2][n2][1] + b1;
                dst[o0 * KP + t0 + 8]       = acc[m2][n2][2] + b0;
                dst[(o0 + 1) * KP + t0 + 8] = acc[m2][n2][3] + b1;
            }
        __syncthreads();   // mma done -> BF restage safe; QS/KS/VS visible
    }

    // ---- stage Wo[64][64] as B-fragments (kg 0..3) ----
    for (int i = tid; i < 2048; i += 512) {
        int o = i >> 5, cp = i & 31;
        float2 g = *(const float2*)(Wo + (o << 6) + (cp << 1));
        int kg = cp >> 3;
        int lane_f = ((o & 7) << 2) + (cp & 3);
        int reg = (cp >> 2) & 1;
        int X = ((cp >> 2) & 7) << 2;
        int idx = ((((o >> 3) << 2) + kg) * 2 + reg) * 32 + (lane_f ^ X);
        BFH[idx] = pack_bf(g.x, g.y);
        BFL[idx] = pack_bf(g.x - bfr(g.x), g.y - bfr(g.y));
    }

    // ---- causal attention (fp32 f32x2, balanced), output -> A-frags ----
    {
        const int gh = w & 3, rr = w >> 2;
#pragma unroll
        for (int hp = 0; hp < 2; ++hp) {
            const int h = gh + 4 * hp;
            const int t = hp ? (127 - ((rr << 5) + lane)) : ((rr << 5) + lane);
            const float* qb = QS + h * 8 * KP;
            const float* kb = KS + h * 8 * KP;
            const float* vb = VS + h * 8 * KP;

            u64 qd2[8];
#pragma unroll
            for (int d = 0; d < 8; ++d) {
                float qv = qb[d * KP + t] * 0.35355339059327373f;
                qd2[d] = pk2(qv, qv);
            }
            float l = 0.f;
            u64 a2[8];
#pragma unroll
            for (int d = 0; d < 8; ++d) a2[d] = 0ULL;

            for (int s0 = 0; s0 <= t; s0 += 4) {
                u64 s01 = 0ULL, s23 = 0ULL;
#pragma unroll
                for (int d = 0; d < 8; ++d) {
                    ulonglong2 kv = *(const ulonglong2*)&kb[d * KP + s0];
                    s01 = ffma2(qd2[d], kv.x, s01);
                    s23 = ffma2(qd2[d], kv.y, s23);
                }
                float2 ea = upk2(s01), eb = upk2(s23);
                float p0 = __expf(ea.x);
                float p1 = (s0 + 1 <= t) ? __expf(ea.y) : 0.f;
                float p2 = (s0 + 2 <= t) ? __expf(eb.x) : 0.f;
                float p3 = (s0 + 3 <= t) ? __expf(eb.y) : 0.f;
                l += (p0 + p1) + (p2 + p3);
                u64 p01 = pk2(p0, p1), p23 = pk2(p2, p3);
#pragma unroll
                for (int d = 0; d < 8; ++d) {
                    ulonglong2 vv = *(const ulonglong2*)&vb[d * KP + s0];
                    a2[d] = ffma2(p01, vv.x, a2[d]);
                    a2[d] = ffma2(p23, vv.y, a2[d]);
                }
            }
            float inv = __fdividef(1.0f, l);
            float o8[8];
#pragma unroll
            for (int d = 0; d < 8; ++d) {
                float2 aa = upk2(a2[d]);
                o8[d] = (aa.x + aa.y) * inv;
            }
            // write as out-proj A-frags: c = h*8 + (0..7)
            int tt = t >> 4, kg2 = h >> 1;
            int reg = ((t & 15) >> 3) + ((h & 1) << 1);
            int X = (t >> 3) & 3;
            int basei = ((tt * 4 + kg2) * 4 + reg) * 32 + ((t & 7) << 2);
#pragma unroll
            for (int j = 0; j < 4; ++j) {
                float e0 = o8[2 * j], e1 = o8[2 * j + 1];
                AFH[basei + (j ^ X)] = pack_bf(e0, e1);
                AFL[basei + (j ^ X)] = pack_bf(e0 - bfr(e0), e1 - bfr(e1));
            }
        }
    }
    __syncthreads();

    // ---- out projection (kg 0..3) + bias + ReLU -> global ----
    {
        float acc[2][2][4];
#pragma unroll
        for (int m2 = 0; m2 < 2; ++m2)
#pragma unroll
            for (int n2 = 0; n2 < 2; ++n2)
#pragma unroll
                for (int j = 0; j < 4; ++j) acc[m2][n2][j] = 0.f;

#pragma unroll
        for (int kg = 0; kg < 4; ++kg) {
            u32 Ah[2][4], Al[2][4], Bh[2][2], Bl[2][2];
#pragma unroll
            for (int m2 = 0; m2 < 2; ++m2) {
                int tt = mt * 2 + m2;
#pragma unroll
                for (int r = 0; r < 4; ++r) {
                    int X = (tt * 2 + (r & 1)) & 3;
                    int idx = ((tt * 4 + kg) * 4 + r) * 32 + (lane ^ X);
                    Ah[m2][r] = AFH[idx];
                    Al[m2][r] = AFL[idx];
                }
            }
#pragma unroll
            for (int n2 = 0; n2 < 2; ++n2) {
                int ot = nq * 2 + n2;
#pragma unroll
                for (int r = 0; r < 2; ++r) {
                    int X = ((kg * 2 + r) & 7) << 2;
                    int idx = ((ot * 4 + kg) * 2 + r) * 32 + (lane ^ X);
                    Bh[n2][r] = BFH[idx];
                    Bl[n2][r] = BFL[idx];
                }
            }
#pragma unroll
            for (int m2 = 0; m2 < 2; ++m2)
#pragma unroll
                for (int n2 = 0; n2 < 2; ++n2) {
                    mma16816(acc[m2][n2], Ah[m2], Bh[n2]);
                    mma16816(acc[m2][n2], Ah[m2], Bl[n2]);
                    mma16816(acc[m2][n2], Al[m2], Bh[n2]);
                }
        }

#pragma unroll
        for (int m2 = 0; m2 < 2; ++m2)
#pragma unroll
            for (int n2 = 0; n2 < 2; ++n2) {
                int t0 = ((mt * 2 + m2) << 4) + gid;
                int o0 = ((nq * 2 + n2) << 3) + (tig << 1);
                float b0 = bias[192 + o0], b1 = bias[192 + o0 + 1];
                long base0 = ((long)(b * 64 + o0) * V_ + v) * T_;
                long base1 = base0 + (long)V_ * T_;
                out[base0 + t0]     = fmaxf(acc[m2][n2][0] + b0, 0.f);
                out[base1 + t0]     = fmaxf(acc[m2][n2][1] + b1, 0.f);
                out[base0 + t0 + 8] = fmaxf(acc[m2][n2][2] + b0, 0.f);
                out[base1 + t0 + 8] = fmaxf(acc[m2][n2][3] + b1, 0.f);
            }
    }
}

// ---------------------------------------------------------------------------
extern "C" void kernel_launch(void* const* d_in, const int* in_sizes, int n_in,
                              void* d_out, int out_size)
{
    (void)in_sizes; (void)n_in; (void)out_size;
    const float* x  = (const float*)d_in[0];
    const float* te = (const float*)d_in[1];
    const float* Wq = (const float*)d_in[2];
    const float* bq = (const float*)d_in[3];
    const float* Wk = (const float*)d_in[4];
    const float* bk = (const float*)d_in[5];
    const float* Wv = (const float*)d_in[6];
    const float* bv = (const float*)d_in[7];
    const float* Wo = (const float*)d_in[8];
    const float* bo = (const float*)d_in[9];
    float* out = (float*)d_out;

    cudaFuncSetAttribute(tatt_hmma, cudaFuncAttributeMaxDynamicSharedMemorySize, SMEM_TOTAL);
    tatt_hmma<<<NBLK, 512, SMEM_TOTAL>>>(x, te, Wq, bq, Wk, bk, Wv, bv, Wo, bo, out);
}